// round 9
// baseline (speedup 1.0000x reference)
#include <cuda_runtime.h>

// SSIM loss, fused streaming kernel — (s,d)=(x+y,x-y) transform, two packed
// f32x2 rings (R6 structure), taller 128x128 tile to cut halo row overhead
// (138 rows / 128 outputs = 1.078x vs 1.203x at TH=64).
// 16x3x512x512 fp32 pred/target -> scalar 1 - mean(ssim_map).

#define IMG   512
#define PLANES 48
#define KW    11
#define KR    5
#define TW    128
#define TH    128
#define SW    (TW + 2*KR)        // 138
#define NTHREADS 128
#define GRIDX (IMG/TW)           // 4
#define GRIDY (IMG/TH)           // 4
#define NBLK  (GRIDX*GRIDY*PLANES)  // 768
#define NPIXD ((double)PLANES * IMG * IMG)

typedef unsigned long long u64;

__device__ double       g_sum;
__device__ unsigned int g_cnt;

__device__ __forceinline__ u64 pk2(float x, float y) {
    u64 r; asm("mov.b64 %0, {%1, %2};" : "=l"(r) : "f"(x), "f"(y)); return r;
}
__device__ __forceinline__ void upk2(u64 v, float& x, float& y) {
    asm("mov.b64 {%0, %1}, %2;" : "=f"(x), "=f"(y) : "l"(v));
}
__device__ __forceinline__ u64 fma2(u64 a, u64 b, u64 c) {
    u64 d; asm("fma.rn.f32x2 %0, %1, %2, %3;" : "=l"(d) : "l"(a), "l"(b), "l"(c));
    return d;
}
__device__ __forceinline__ u64 mul2(u64 a, u64 b) {
    u64 d; asm("mul.rn.f32x2 %0, %1, %2;" : "=l"(d) : "l"(a), "l"(b));
    return d;
}

__global__ __launch_bounds__(NTHREADS, 5)
void ssim_kernel(const float* __restrict__ pred,
                 const float* __restrict__ targ,
                 float* __restrict__ out)
{
    constexpr float W[KW] = {
        0.00102838f, 0.00759876f, 0.03600077f, 0.10936069f, 0.21300554f,
        0.26601173f,
        0.21300554f, 0.10936069f, 0.03600077f, 0.00759876f, 0.00102838f
    };
    constexpr float C1 = 0.0001f;
    constexpr float C2 = 0.0009f;

    __shared__ float2 sb[2][SW];      // interleaved (s, d) staging rows
    __shared__ float  wsum[4];

    const int t  = threadIdx.x;
    const int x0 = blockIdx.x * TW;
    const int y0 = blockIdx.y * TH;
    const float* __restrict__ xin = pred + (size_t)blockIdx.z * IMG * IMG;
    const float* __restrict__ yin = targ + (size_t)blockIdx.z * IMG * IMG;

    const int  gx0  = x0 - KR + t;
    const int  gx1  = gx0 + TW;
    const bool tail = (t < SW - TW);

    // load one padded row; return (s,d) = (x+y, x-y) pairs
    auto ldrow = [&](int j, float& s0, float& d0, float& s1, float& d1) {
        const int  gy  = y0 - KR + j;
        const bool rok = (gy >= 0) && (gy < IMG);
        const bool ok0 = rok && (gx0 >= 0) && (gx0 < IMG);
        const bool ok1 = rok && tail && (gx1 < IMG);
        const long b = (long)gy * IMG;
        const float ax0 = ok0 ? xin[b + gx0] : 0.0f;
        const float ay0 = ok0 ? yin[b + gx0] : 0.0f;
        const float ax1 = ok1 ? xin[b + gx1] : 0.0f;
        const float ay1 = ok1 ? yin[b + gx1] : 0.0f;
        s0 = ax0 + ay0;  d0 = ax0 - ay0;
        s1 = ax1 + ay1;  d1 = ax1 - ay1;
    };

    // 6 distinct packed weights (Gaussian symmetry)
    u64 WW[6];
    #pragma unroll
    for (int k = 0; k < 6; ++k) WW[k] = pk2(W[k], W[k]);
    const u64 NEG1 = pk2(-1.0f, -1.0f);
    const u64 Z64  = 0ull;

    // ring accumulators: packed (mu_s, mu_d) and (E[s^2], E[d^2])
    u64 aMU[11], aSQ[11];
    #pragma unroll
    for (int s = 0; s < 11; ++s) { aMU[s] = Z64; aSQ[s] = Z64; }

    float tsum = 0.0f;

    // preload + stage row 0
    {
        float s0, d0, s1, d1;
        ldrow(0, s0, d0, s1, d1);
        sb[0][t] = make_float2(s0, d0);
        if (tail) sb[0][TW + t] = make_float2(s1, d1);
    }
    __syncthreads();

    // 12 full 11-row blocks + 6-row epilogue: rows j = 0..137 (138 rows)
    for (int jb = 0; jb <= 12; ++jb) {
        #pragma unroll
        for (int u = 0; u < 11; ++u) {
            if (jb == 12 && u >= 6) break;    // epilogue: only u = 0..5
            const int j = jb * 11 + u;

            // prefetch next row (overlaps compute)
            float ns0, nd0, ns1, nd1;
            ldrow(j + 1, ns0, nd0, ns1, nd1);

            // ---- horizontal blur: 3 packed ops per tap ----
            const u64* s = (const u64*)sb[j & 1];
            u64 hmu = Z64, hsq = Z64;
            #pragma unroll
            for (int k = 0; k < KW; ++k) {
                const int kw = (k < 6) ? k : 10 - k;    // literal
                const u64 p  = s[t + k];                // (s, d) LDS.64
                const u64 pp = mul2(p, p);              // (s^2, d^2)
                hmu = fma2(WW[kw], p,  hmu);
                hsq = fma2(WW[kw], pp, hsq);
            }

            // ---- vertical ring update: 2 packed ops per tap ----
            #pragma unroll
            for (int p = 0; p < KW; ++p) {
                const int ss = (u - p + 11) % 11;       // literal
                const int pw = (p < 6) ? p : 10 - p;    // literal
                aMU[ss] = fma2(WW[pw], hmu, aMU[ss]);
                aSQ[ss] = fma2(WW[pw], hsq, aSQ[ss]);
            }

            // ---- finalize output row o = j-10, reset slot ----
            {
                const int so = (u + 1) % 11;
                const int o  = j - (KW - 1);
                if (o >= 0 && o < TH) {
                    const u64 mu  = aMU[so];
                    const u64 mu2 = mul2(mu, mu);             // (mus^2, mud^2)
                    const u64 sg  = fma2(mu2, NEG1, aSQ[so]); // (sig_s, sig_d)
                    float g0, g1, v0, v1;
                    upk2(mu2, g0, g1);
                    upk2(sg,  v0, v1);
                    // 2*mu_xy=(g0-g1)/2 ; mu_x^2+mu_y^2=(g0+g1)/2
                    // 2*sg_xy=(v0-v1)/2 ; sg_x+sg_y    =(v0+v1)/2
                    const float num = (0.5f*(g0 - g1) + C1) * (0.5f*(v0 - v1) + C2);
                    const float den = (0.5f*(g0 + g1) + C1) * (0.5f*(v0 + v1) + C2);
                    tsum += __fdividef(num, den);
                }
                aMU[so] = Z64; aSQ[so] = Z64;
            }

            // stage prefetched row j+1 into the other buffer (overwrites data
            // last read in iter j-1, fenced by that iteration's barrier)
            const int nb = (j + 1) & 1;
            sb[nb][t] = make_float2(ns0, nd0);
            if (tail) sb[nb][TW + t] = make_float2(ns1, nd1);
            __syncthreads();
        }
    }

    // ---- reduction: warp -> block -> global ----
    #pragma unroll
    for (int off = 16; off > 0; off >>= 1)
        tsum += __shfl_down_sync(0xffffffffu, tsum, off);
    if ((t & 31) == 0) wsum[t >> 5] = tsum;
    __syncthreads();

    if (t == 0) {
        const double bs = (double)wsum[0] + (double)wsum[1]
                        + (double)wsum[2] + (double)wsum[3];
        atomicAdd(&g_sum, bs);
        __threadfence();
        const unsigned r = atomicAdd(&g_cnt, 1u);
        if (r == NBLK - 1u) {
            const double sall = g_sum;
            out[0] = (float)(1.0 - sall / NPIXD);
            g_sum = 0.0;
            __threadfence();
            g_cnt = 0u;
        }
    }
}

extern "C" void kernel_launch(void* const* d_in, const int* in_sizes, int n_in,
                              void* d_out, int out_size)
{
    const float* pred = (const float*)d_in[0];
    const float* targ = (const float*)d_in[1];
    float* out = (float*)d_out;

    dim3 grid(GRIDX, GRIDY, PLANES);   // 4 x 4 x 48 = 768 blocks
    ssim_kernel<<<grid, NTHREADS>>>(pred, targ, out);
}

// round 10
// speedup vs baseline: 1.0480x; 1.0480x over previous
#include <cuda_runtime.h>

// SSIM loss, fused streaming kernel — (s,d)=(x+y,x-y) transform, two packed
// f32x2 rings (R6 base, TH=64), h-blur accumulation split into even/odd
// partial chains to break the RAW-latency serialization. sm_103a packed math.
// 16x3x512x512 fp32 pred/target -> scalar 1 - mean(ssim_map).

#define IMG   512
#define PLANES 48
#define KW    11
#define KR    5
#define TW    128
#define TH    64
#define NRB   7                  // 7*11 = 77 rows streamed >= TH+10
#define SW    (TW + 2*KR)        // 138
#define NTHREADS 128
#define GRIDX (IMG/TW)           // 4
#define GRIDY (IMG/TH)           // 8
#define NBLK  (GRIDX*GRIDY*PLANES)  // 1536
#define NPIXD ((double)PLANES * IMG * IMG)

typedef unsigned long long u64;

__device__ double       g_sum;
__device__ unsigned int g_cnt;

__device__ __forceinline__ u64 pk2(float x, float y) {
    u64 r; asm("mov.b64 %0, {%1, %2};" : "=l"(r) : "f"(x), "f"(y)); return r;
}
__device__ __forceinline__ void upk2(u64 v, float& x, float& y) {
    asm("mov.b64 {%0, %1}, %2;" : "=f"(x), "=f"(y) : "l"(v));
}
__device__ __forceinline__ u64 fma2(u64 a, u64 b, u64 c) {
    u64 d; asm("fma.rn.f32x2 %0, %1, %2, %3;" : "=l"(d) : "l"(a), "l"(b), "l"(c));
    return d;
}
__device__ __forceinline__ u64 mul2(u64 a, u64 b) {
    u64 d; asm("mul.rn.f32x2 %0, %1, %2;" : "=l"(d) : "l"(a), "l"(b));
    return d;
}
__device__ __forceinline__ u64 add2(u64 a, u64 b) {
    u64 d; asm("add.rn.f32x2 %0, %1, %2;" : "=l"(d) : "l"(a), "l"(b));
    return d;
}

__global__ __launch_bounds__(NTHREADS, 5)
void ssim_kernel(const float* __restrict__ pred,
                 const float* __restrict__ targ,
                 float* __restrict__ out)
{
    constexpr float W[KW] = {
        0.00102838f, 0.00759876f, 0.03600077f, 0.10936069f, 0.21300554f,
        0.26601173f,
        0.21300554f, 0.10936069f, 0.03600077f, 0.00759876f, 0.00102838f
    };
    constexpr float C1 = 0.0001f;
    constexpr float C2 = 0.0009f;

    __shared__ float2 sb[2][SW];      // interleaved (s, d) staging rows
    __shared__ float  wsum[4];

    const int t  = threadIdx.x;
    const int x0 = blockIdx.x * TW;
    const int y0 = blockIdx.y * TH;
    const float* __restrict__ xin = pred + (size_t)blockIdx.z * IMG * IMG;
    const float* __restrict__ yin = targ + (size_t)blockIdx.z * IMG * IMG;

    const int  gx0  = x0 - KR + t;
    const int  gx1  = gx0 + TW;
    const bool tail = (t < SW - TW);

    // load one padded row; return (s,d) = (x+y, x-y) pairs
    auto ldrow = [&](int j, float& s0, float& d0, float& s1, float& d1) {
        const int  gy  = y0 - KR + j;
        const bool rok = (gy >= 0) && (gy < IMG);
        const bool ok0 = rok && (gx0 >= 0) && (gx0 < IMG);
        const bool ok1 = rok && tail && (gx1 < IMG);
        const long b = (long)gy * IMG;
        const float ax0 = ok0 ? xin[b + gx0] : 0.0f;
        const float ay0 = ok0 ? yin[b + gx0] : 0.0f;
        const float ax1 = ok1 ? xin[b + gx1] : 0.0f;
        const float ay1 = ok1 ? yin[b + gx1] : 0.0f;
        s0 = ax0 + ay0;  d0 = ax0 - ay0;
        s1 = ax1 + ay1;  d1 = ax1 - ay1;
    };

    // 6 distinct packed weights (Gaussian symmetry)
    u64 WW[6];
    #pragma unroll
    for (int k = 0; k < 6; ++k) WW[k] = pk2(W[k], W[k]);
    const u64 NEG1 = pk2(-1.0f, -1.0f);
    const u64 Z64  = 0ull;

    // ring accumulators: packed (mu_s, mu_d) and (E[s^2], E[d^2])
    u64 aMU[11], aSQ[11];
    #pragma unroll
    for (int s = 0; s < 11; ++s) { aMU[s] = Z64; aSQ[s] = Z64; }

    float tsum = 0.0f;

    // preload + stage row 0
    {
        float s0, d0, s1, d1;
        ldrow(0, s0, d0, s1, d1);
        sb[0][t] = make_float2(s0, d0);
        if (tail) sb[0][TW + t] = make_float2(s1, d1);
    }
    __syncthreads();

    for (int jb = 0; jb < NRB; ++jb) {
        #pragma unroll
        for (int u = 0; u < 11; ++u) {
            const int j = jb * 11 + u;

            // prefetch next row (overlaps compute)
            float ns0, nd0, ns1, nd1;
            ldrow(j + 1, ns0, nd0, ns1, nd1);

            // ---- horizontal blur: 4 independent partial chains ----
            const u64* s = (const u64*)sb[j & 1];
            u64 hmuA = Z64, hsqA = Z64;   // even taps k = 0,2,4,6,8,10
            u64 hmuB = Z64, hsqB = Z64;   // odd  taps k = 1,3,5,7,9
            #pragma unroll
            for (int k = 0; k < KW; ++k) {
                const int kw = (k < 6) ? k : 10 - k;    // literal
                const u64 p  = s[t + k];                // (s, d) LDS.64
                const u64 pp = mul2(p, p);              // (s^2, d^2)
                if ((k & 1) == 0) {
                    hmuA = fma2(WW[kw], p,  hmuA);
                    hsqA = fma2(WW[kw], pp, hsqA);
                } else {
                    hmuB = fma2(WW[kw], p,  hmuB);
                    hsqB = fma2(WW[kw], pp, hsqB);
                }
            }
            const u64 hmu = add2(hmuA, hmuB);
            const u64 hsq = add2(hsqA, hsqB);

            // ---- vertical ring update: 2 packed ops per tap (independent) ----
            #pragma unroll
            for (int p = 0; p < KW; ++p) {
                const int ss = (u - p + 11) % 11;       // literal
                const int pw = (p < 6) ? p : 10 - p;    // literal
                aMU[ss] = fma2(WW[pw], hmu, aMU[ss]);
                aSQ[ss] = fma2(WW[pw], hsq, aSQ[ss]);
            }

            // ---- finalize output row o = j-10, reset slot ----
            {
                const int so = (u + 1) % 11;
                const int o  = j - (KW - 1);
                if (o >= 0 && o < TH) {
                    const u64 mu  = aMU[so];
                    const u64 mu2 = mul2(mu, mu);             // (mus^2, mud^2)
                    const u64 sg  = fma2(mu2, NEG1, aSQ[so]); // (sig_s, sig_d)
                    float g0, g1, v0, v1;
                    upk2(mu2, g0, g1);
                    upk2(sg,  v0, v1);
                    // 2*mu_xy=(g0-g1)/2 ; mu_x^2+mu_y^2=(g0+g1)/2
                    // 2*sg_xy=(v0-v1)/2 ; sg_x+sg_y    =(v0+v1)/2
                    const float num = (0.5f*(g0 - g1) + C1) * (0.5f*(v0 - v1) + C2);
                    const float den = (0.5f*(g0 + g1) + C1) * (0.5f*(v0 + v1) + C2);
                    tsum += __fdividef(num, den);
                }
                aMU[so] = Z64; aSQ[so] = Z64;
            }

            // stage prefetched row j+1 into the other buffer (overwrites data
            // last read in iter j-1, fenced by that iteration's barrier)
            const int nb = (j + 1) & 1;
            sb[nb][t] = make_float2(ns0, nd0);
            if (tail) sb[nb][TW + t] = make_float2(ns1, nd1);
            __syncthreads();
        }
    }

    // ---- reduction: warp -> block -> global ----
    #pragma unroll
    for (int off = 16; off > 0; off >>= 1)
        tsum += __shfl_down_sync(0xffffffffu, tsum, off);
    if ((t & 31) == 0) wsum[t >> 5] = tsum;
    __syncthreads();

    if (t == 0) {
        const double bs = (double)wsum[0] + (double)wsum[1]
                        + (double)wsum[2] + (double)wsum[3];
        atomicAdd(&g_sum, bs);
        __threadfence();
        const unsigned r = atomicAdd(&g_cnt, 1u);
        if (r == NBLK - 1u) {
            const double sall = g_sum;
            out[0] = (float)(1.0 - sall / NPIXD);
            g_sum = 0.0;
            __threadfence();
            g_cnt = 0u;
        }
    }
}

extern "C" void kernel_launch(void* const* d_in, const int* in_sizes, int n_in,
                              void* d_out, int out_size)
{
    const float* pred = (const float*)d_in[0];
    const float* targ = (const float*)d_in[1];
    float* out = (float*)d_out;

    dim3 grid(GRIDX, GRIDY, PLANES);   // 4 x 8 x 48 = 1536 blocks
    ssim_kernel<<<grid, NTHREADS>>>(pred, targ, out);
}

// round 11
// speedup vs baseline: 1.0670x; 1.0182x over previous
#include <cuda_runtime.h>
#include <cuda_fp16.h>

// SSIM loss, fused streaming kernel — (s,d)=(x+y,x-y) transform; h-blur in
// packed fp32 (f32x2), vertical ring accumulators in half2 (HFMA2) to cut
// ring registers 44->22 and reach 6 CTAs/SM. 16x3x512x512 fp32 -> scalar.

#define IMG   512
#define PLANES 48
#define KW    11
#define KR    5
#define TW    128
#define TH    64
#define NRB   7                  // 7*11 = 77 rows streamed >= TH+10
#define SW    (TW + 2*KR)        // 138
#define NTHREADS 128
#define GRIDX (IMG/TW)           // 4
#define GRIDY (IMG/TH)           // 8
#define NBLK  (GRIDX*GRIDY*PLANES)  // 1536
#define NPIXD ((double)PLANES * IMG * IMG)

typedef unsigned long long u64;

__device__ double       g_sum;
__device__ unsigned int g_cnt;

__device__ __forceinline__ u64 pk2(float x, float y) {
    u64 r; asm("mov.b64 %0, {%1, %2};" : "=l"(r) : "f"(x), "f"(y)); return r;
}
__device__ __forceinline__ void upk2(u64 v, float& x, float& y) {
    asm("mov.b64 {%0, %1}, %2;" : "=f"(x), "=f"(y) : "l"(v));
}
__device__ __forceinline__ u64 fma2(u64 a, u64 b, u64 c) {
    u64 d; asm("fma.rn.f32x2 %0, %1, %2, %3;" : "=l"(d) : "l"(a), "l"(b), "l"(c));
    return d;
}
__device__ __forceinline__ u64 mul2(u64 a, u64 b) {
    u64 d; asm("mul.rn.f32x2 %0, %1, %2;" : "=l"(d) : "l"(a), "l"(b));
    return d;
}

__global__ __launch_bounds__(NTHREADS, 6)
void ssim_kernel(const float* __restrict__ pred,
                 const float* __restrict__ targ,
                 float* __restrict__ out)
{
    constexpr float W[KW] = {
        0.00102838f, 0.00759876f, 0.03600077f, 0.10936069f, 0.21300554f,
        0.26601173f,
        0.21300554f, 0.10936069f, 0.03600077f, 0.00759876f, 0.00102838f
    };
    constexpr float C1 = 0.0001f;
    constexpr float C2 = 0.0009f;

    __shared__ float2 sb[2][SW];      // interleaved (s, d) staging rows
    __shared__ float  wsum[4];

    const int t  = threadIdx.x;
    const int x0 = blockIdx.x * TW;
    const int y0 = blockIdx.y * TH;
    const float* __restrict__ xin = pred + (size_t)blockIdx.z * IMG * IMG;
    const float* __restrict__ yin = targ + (size_t)blockIdx.z * IMG * IMG;

    const int  gx0  = x0 - KR + t;
    const int  gx1  = gx0 + TW;
    const bool tail = (t < SW - TW);

    // load one padded row; return (s,d) = (x+y, x-y) pairs
    auto ldrow = [&](int j, float& s0, float& d0, float& s1, float& d1) {
        const int  gy  = y0 - KR + j;
        const bool rok = (gy >= 0) && (gy < IMG);
        const bool ok0 = rok && (gx0 >= 0) && (gx0 < IMG);
        const bool ok1 = rok && tail && (gx1 < IMG);
        const long b = (long)gy * IMG;
        const float ax0 = ok0 ? xin[b + gx0] : 0.0f;
        const float ay0 = ok0 ? yin[b + gx0] : 0.0f;
        const float ax1 = ok1 ? xin[b + gx1] : 0.0f;
        const float ay1 = ok1 ? yin[b + gx1] : 0.0f;
        s0 = ax0 + ay0;  d0 = ax0 - ay0;
        s1 = ax1 + ay1;  d1 = ax1 - ay1;
    };

    // packed fp32 weights for the horizontal stage (6 distinct by symmetry)
    u64 WW[6];
    #pragma unroll
    for (int k = 0; k < 6; ++k) WW[k] = pk2(W[k], W[k]);
    const u64 Z64 = 0ull;

    // half2 weights for the vertical stage
    half2 W2[6];
    #pragma unroll
    for (int k = 0; k < 6; ++k) W2[k] = __floats2half2_rn(W[k], W[k]);
    const half2 Z16 = __floats2half2_rn(0.f, 0.f);

    // ring accumulators in half2: (mu_s, mu_d) and (E[s^2], E[d^2])
    half2 aMU[11], aSQ[11];
    #pragma unroll
    for (int s = 0; s < 11; ++s) { aMU[s] = Z16; aSQ[s] = Z16; }

    float tsum = 0.0f;

    // preload + stage row 0
    {
        float s0, d0, s1, d1;
        ldrow(0, s0, d0, s1, d1);
        sb[0][t] = make_float2(s0, d0);
        if (tail) sb[0][TW + t] = make_float2(s1, d1);
    }
    __syncthreads();

    for (int jb = 0; jb < NRB; ++jb) {
        #pragma unroll
        for (int u = 0; u < 11; ++u) {
            const int j = jb * 11 + u;

            // prefetch next row (overlaps compute)
            float ns0, nd0, ns1, nd1;
            ldrow(j + 1, ns0, nd0, ns1, nd1);

            // ---- horizontal blur: packed fp32, 3 ops per tap ----
            const u64* s = (const u64*)sb[j & 1];
            u64 hmu = Z64, hsq = Z64;
            #pragma unroll
            for (int k = 0; k < KW; ++k) {
                const int kw = (k < 6) ? k : 10 - k;    // literal
                const u64 p  = s[t + k];                // (s, d) LDS.64
                const u64 pp = mul2(p, p);              // (s^2, d^2)
                hmu = fma2(WW[kw], p,  hmu);
                hsq = fma2(WW[kw], pp, hsq);
            }

            // convert h-blurred row values to half2 for the vertical stage
            float hm0, hm1, hq0, hq1;
            upk2(hmu, hm0, hm1);
            upk2(hsq, hq0, hq1);
            const half2 hm2 = __floats2half2_rn(hm0, hm1);
            const half2 hq2 = __floats2half2_rn(hq0, hq1);

            // ---- vertical ring update: 2 HFMA2 per tap (literal slots) ----
            #pragma unroll
            for (int p = 0; p < KW; ++p) {
                const int ss = (u - p + 11) % 11;       // literal
                const int pw = (p < 6) ? p : 10 - p;    // literal
                aMU[ss] = __hfma2(W2[pw], hm2, aMU[ss]);
                aSQ[ss] = __hfma2(W2[pw], hq2, aSQ[ss]);
            }

            // ---- finalize output row o = j-10, reset slot ----
            {
                const int so = (u + 1) % 11;
                const int o  = j - (KW - 1);
                if (o >= 0 && o < TH) {
                    const float2 mu = __half22float2(aMU[so]);
                    const float2 sq = __half22float2(aSQ[so]);
                    const float g0 = mu.x * mu.x;       // mus^2
                    const float g1 = mu.y * mu.y;       // mud^2
                    const float v0 = sq.x - g0;         // sig_s
                    const float v1 = sq.y - g1;         // sig_d
                    // 2*mu_xy=(g0-g1)/2 ; mu_x^2+mu_y^2=(g0+g1)/2
                    // 2*sg_xy=(v0-v1)/2 ; sg_x+sg_y    =(v0+v1)/2
                    const float num = (0.5f*(g0 - g1) + C1) * (0.5f*(v0 - v1) + C2);
                    const float den = (0.5f*(g0 + g1) + C1) * (0.5f*(v0 + v1) + C2);
                    tsum += __fdividef(num, den);
                }
                aMU[so] = Z16; aSQ[so] = Z16;
            }

            // stage prefetched row j+1 into the other buffer (overwrites data
            // last read in iter j-1, fenced by that iteration's barrier)
            const int nb = (j + 1) & 1;
            sb[nb][t] = make_float2(ns0, nd0);
            if (tail) sb[nb][TW + t] = make_float2(ns1, nd1);
            __syncthreads();
        }
    }

    // ---- reduction: warp -> block -> global ----
    #pragma unroll
    for (int off = 16; off > 0; off >>= 1)
        tsum += __shfl_down_sync(0xffffffffu, tsum, off);
    if ((t & 31) == 0) wsum[t >> 5] = tsum;
    __syncthreads();

    if (t == 0) {
        const double bs = (double)wsum[0] + (double)wsum[1]
                        + (double)wsum[2] + (double)wsum[3];
        atomicAdd(&g_sum, bs);
        __threadfence();
        const unsigned r = atomicAdd(&g_cnt, 1u);
        if (r == NBLK - 1u) {
            const double sall = g_sum;
            out[0] = (float)(1.0 - sall / NPIXD);
            g_sum = 0.0;
            __threadfence();
            g_cnt = 0u;
        }
    }
}

extern "C" void kernel_launch(void* const* d_in, const int* in_sizes, int n_in,
                              void* d_out, int out_size)
{
    const float* pred = (const float*)d_in[0];
    const float* targ = (const float*)d_in[1];
    float* out = (float*)d_out;

    dim3 grid(GRIDX, GRIDY, PLANES);   // 4 x 8 x 48 = 1536 blocks
    ssim_kernel<<<grid, NTHREADS>>>(pred, targ, out);
}